// round 2
// baseline (speedup 1.0000x reference)
#include <cuda_runtime.h>
#include <cstdint>
#include <math.h>

#define NB   32
#define NC   256
#define NS   1024
#define NBS  (NB * NS)     // 32768
#define NCS  (NC * NS)     // 262144

// ---------------- device scratch (no allocations allowed) ----------------
__device__ float g_ink_b[NBS];                 // 1/||k_b column||
__device__ float g_inq [NBS];                  // 1/||q_grid column||
__device__ float g_inkg[NBS];                  // 1/||k_grid column||
__device__ float g_qgt[(size_t)NB * NS * NC];  // normalized q_grid, [B,S,C]
__device__ float g_kgt[(size_t)NB * NS * NC];  // normalized k_grid, [B,S,C]
__device__ unsigned long long g_arg[NBS];      // packed (value, ~j) argmax
__device__ int   g_negidx[NB];
__device__ float g_loss;

// ---------------- Kernel A: column norms + state reset ----------------
__global__ void norms_init_kernel(const float* __restrict__ kb,
                                  const float* __restrict__ qg,
                                  const float* __restrict__ kg) {
    int t = blockIdx.x * blockDim.x + threadIdx.x;   // 0..32767
    int b = t >> 10, s = t & 1023;
    const float* p1 = kb + b * NCS + s;
    const float* p2 = qg + b * NCS + s;
    const float* p3 = kg + b * NCS + s;
    float s1 = 0.f, s2 = 0.f, s3 = 0.f;
#pragma unroll 8
    for (int c = 0; c < NC; c++) {
        float v1 = p1[c * NS], v2 = p2[c * NS], v3 = p3[c * NS];
        s1 += v1 * v1; s2 += v2 * v2; s3 += v3 * v3;
    }
    g_ink_b[t] = 1.0f / fmaxf(sqrtf(s1), 1e-12f);
    g_inq [t]  = 1.0f / fmaxf(sqrtf(s2), 1e-12f);
    g_inkg[t]  = 1.0f / fmaxf(sqrtf(s3), 1e-12f);
    g_arg[t] = 0ull;                 // graph replays: must reset every call
    if (t == 0) g_loss = 0.0f;
}

// ---------------- Kernel B: normalize + transpose to [B,S,C] ----------------
__global__ void transpose_kernel(const float* __restrict__ qg,
                                 const float* __restrict__ kg) {
    __shared__ float tile[32][33];
    int z = blockIdx.z;              // 0..63: (b, tensor)
    int b = z >> 1;
    int tensor = z & 1;
    const float* in  = tensor ? kg     : qg;
    const float* inv = tensor ? g_inkg : g_inq;
    float*       out = tensor ? g_kgt  : g_qgt;
    int c0 = blockIdx.y * 32;
    int s0 = blockIdx.x * 32;
    int x = threadIdx.x, y = threadIdx.y;     // (32, 8)
#pragma unroll
    for (int cc = 0; cc < 32; cc += 8)
        tile[y + cc][x] = in[(size_t)b * NCS + (size_t)(c0 + y + cc) * NS + s0 + x];
    __syncthreads();
#pragma unroll
    for (int cc = 0; cc < 32; cc += 8) {
        int s = s0 + y + cc;
        out[((size_t)b * NS + s) * NC + c0 + x] = tile[x][y + cc] * inv[b * NS + s];
    }
}

// ---------------- Kernel C: fused SGEMM + scaled argmax ----------------
// sim[b][i][j] = sum_c q_b[b][c][i] * k_b[b][c][j];   argmax_j (sim * ink_b[j])
// (q row norm is constant over j -> argmax invariant, skip it)
__device__ __forceinline__ unsigned long long pack_key(float v, int j) {
    unsigned int u = __float_as_uint(v);
    u = (u & 0x80000000u) ? ~u : (u | 0x80000000u);     // order-preserving
    return ((unsigned long long)u << 32) | (unsigned int)(0xFFFFFFFFu - (unsigned int)j);
}

__global__ __launch_bounds__(256, 2)
void gemm_argmax_kernel(const float* __restrict__ qb, const float* __restrict__ kb) {
    __shared__ float As[16][128];
    __shared__ float Bs[16][128];
    int b  = blockIdx.z;
    int i0 = blockIdx.y * 128;
    int j0 = blockIdx.x * 128;
    const float* Q = qb + (size_t)b * NCS;
    const float* K = kb + (size_t)b * NCS;
    int tid = threadIdx.x;
    int tx = tid & 15, ty = tid >> 4;

    float acc[8][8];
#pragma unroll
    for (int r = 0; r < 8; r++)
#pragma unroll
        for (int c = 0; c < 8; c++) acc[r][c] = 0.f;

    for (int kc = 0; kc < NC; kc += 16) {
#pragma unroll
        for (int v = 0; v < 2; v++) {
            int idx = tid + v * 256;
            int row = idx >> 5, c4 = (idx & 31) << 2;
            *(float4*)&As[row][c4] = *(const float4*)(Q + (size_t)(kc + row) * NS + i0 + c4);
            *(float4*)&Bs[row][c4] = *(const float4*)(K + (size_t)(kc + row) * NS + j0 + c4);
        }
        __syncthreads();
#pragma unroll
        for (int k = 0; k < 16; k++) {
            float a[8], bb[8];
            *(float4*)&a[0]  = *(const float4*)&As[k][ty * 4];
            *(float4*)&a[4]  = *(const float4*)&As[k][64 + ty * 4];
            *(float4*)&bb[0] = *(const float4*)&Bs[k][tx * 4];
            *(float4*)&bb[4] = *(const float4*)&Bs[k][64 + tx * 4];
#pragma unroll
            for (int r = 0; r < 8; r++)
#pragma unroll
                for (int c = 0; c < 8; c++) acc[r][c] += a[r] * bb[c];
        }
        __syncthreads();
    }

    // epilogue: scale columns by 1/||k_b[j]||, argmax per row (first-max ties)
    float inkv[8];
#pragma unroll
    for (int cc = 0; cc < 8; cc++) {
        int col = (cc < 4) ? (tx * 4 + cc) : (64 + tx * 4 + cc - 4);
        inkv[cc] = g_ink_b[b * NS + j0 + col];
    }
#pragma unroll
    for (int rr = 0; rr < 8; rr++) {
        float best = -3.4e38f; int bj = 0;
#pragma unroll
        for (int cc = 0; cc < 8; cc++) {   // cols ascend with cc -> first-max kept
            int col = (cc < 4) ? (tx * 4 + cc) : (64 + tx * 4 + cc - 4);
            float v = acc[rr][cc] * inkv[cc];
            if (v > best) { best = v; bj = j0 + col; }
        }
        unsigned long long key = pack_key(best, bj);
#pragma unroll
        for (int off = 8; off; off >>= 1) {   // 16-lane groups share a row
            unsigned long long o = __shfl_xor_sync(0xFFFFFFFFu, key, off);
            if (o > key) key = o;
        }
        if (tx == 0) {
            int row = (rr < 4) ? (ty * 4 + rr) : (64 + ty * 4 + rr - 4);
            atomicMax(&g_arg[b * NS + i0 + row], key);
        }
    }
}

// ---------------- Kernel D: jax PARTITIONABLE threefry -> uniform -> neg_idx -
// jax_threefry_partitionable=True (modern default): element with flat index n
// gets counter (hi=0, lo=n); 32-bit output = out0 ^ out1 of the block.
__device__ __forceinline__ void threefry2x32(uint32_t k0, uint32_t k1,
                                             uint32_t x0, uint32_t x1,
                                             uint32_t& o0, uint32_t& o1) {
    uint32_t ks0 = k0, ks1 = k1, ks2 = k0 ^ k1 ^ 0x1BD11BDAu;
    const int r0[4] = {13, 15, 26, 6};
    const int r1[4] = {17, 29, 16, 24};
    x0 += ks0; x1 += ks1;
    uint32_t ks[3] = {ks0, ks1, ks2};
#pragma unroll
    for (int i = 0; i < 5; i++) {
        const int* rr = (i & 1) ? r1 : r0;
#pragma unroll
        for (int j = 0; j < 4; j++) {
            x0 += x1;
            x1 = (x1 << rr[j]) | (x1 >> (32 - rr[j]));
            x1 ^= x0;
        }
        x0 += ks[(i + 1) % 3];
        x1 += ks[(i + 2) % 3] + (uint32_t)(i + 1);
    }
    o0 = x0; o1 = x1;
}

__global__ void negidx_kernel(const int* __restrict__ labels_raw) {
    __shared__ float uf[1024];
    __shared__ int lab[32];
    __shared__ int is64;
    int t = threadIdx.x;   // 1024 threads, one per element of u (32x32)
    uint32_t o0, o1;
    threefry2x32(0u, 42u, 0u, (uint32_t)t, o0, o1);   // counter = (hi=0, lo=n)
    uint32_t bits = o0 ^ o1;                           // partitionable 32-bit fold
    uf[t] = __uint_as_float((bits >> 9) | 0x3f800000u) - 1.0f;
    if (t == 0) {
        // int64 little-endian with small labels => every odd int32 word is 0
        int all0 = 1;
        for (int i = 1; i < 32; i += 2) all0 &= (labels_raw[i] == 0);
        is64 = all0;
    }
    __syncthreads();
    if (t < 32) lab[t] = is64 ? labels_raw[2 * t] : labels_raw[t];
    __syncthreads();
    if (t < 32) {
        int lb = lab[t];
        float best = -2.0f; int bi = 0;
        for (int j = 0; j < 32; j++) {
            float v = (lab[j] != lb) ? uf[t * 32 + j] : -1.0f;
            if (v > best) { best = v; bi = j; }    // first-max ties
        }
        g_negidx[t] = bi;
    }
}

// ---------------- Kernel E: loss terms (warp per (b,i)) ----------------
__global__ void loss_kernel() {
    __shared__ float part[8];
    int wid = threadIdx.x >> 5, lane = threadIdx.x & 31;
    int gw = blockIdx.x * 8 + wid;          // 0..32767
    int b = gw >> 10, i = gw & 1023;
    unsigned long long key = g_arg[gw];
    int idx = (int)(0xFFFFFFFFu - (unsigned int)(key & 0xFFFFFFFFull));
    int nb = g_negidx[b];
    const float4* q  = (const float4*)(g_qgt + (size_t)gw * NC);
    const float4* kp = (const float4*)(g_kgt + ((size_t)b  * NS + idx) * NC);
    const float4* kn = (const float4*)(g_kgt + ((size_t)nb * NS + i)   * NC);
    float dp = 0.f, dn = 0.f;
#pragma unroll
    for (int u = 0; u < 2; u++) {
        int c4 = lane + u * 32;
        float4 qv = q[c4], pv = kp[c4], nv = kn[c4];
        dp += qv.x * pv.x + qv.y * pv.y + qv.z * pv.z + qv.w * pv.w;
        dn += qv.x * nv.x + qv.y * nv.y + qv.z * nv.z + qv.w * nv.w;
    }
#pragma unroll
    for (int off = 16; off; off >>= 1) {
        dp += __shfl_xor_sync(0xFFFFFFFFu, dp, off);
        dn += __shfl_xor_sync(0xFFFFFFFFu, dn, off);
    }
    if (lane == 0) {
        float p = dp * 10.0f;   // / TEMP
        float n = dn * 10.0f;
        part[wid] = logf(expf(p) + expf(n) + 1e-6f) - p;
    }
    __syncthreads();
    if (threadIdx.x == 0) {
        float s = 0.f;
        for (int w = 0; w < 8; w++) s += part[w];
        atomicAdd(&g_loss, s);
    }
}

__global__ void finalize_kernel(float* out) {
    out[0] = g_loss * (1.0f / 32768.0f);   // mean * LAM(=1)
}

// ---------------- entry ----------------
extern "C" void kernel_launch(void* const* d_in, const int* in_sizes, int n_in,
                              void* d_out, int out_size) {
    const float* q_b    = (const float*)d_in[0];
    const float* k_b    = (const float*)d_in[1];
    const float* q_grid = (const float*)d_in[2];
    const float* k_grid = (const float*)d_in[3];
    const int*   labels = (const int*)d_in[4];

    norms_init_kernel<<<128, 256>>>(k_b, q_grid, k_grid);
    transpose_kernel<<<dim3(32, 8, 64), dim3(32, 8)>>>(q_grid, k_grid);
    negidx_kernel<<<1, 1024>>>(labels);
    gemm_argmax_kernel<<<dim3(8, 8, 32), 256>>>(q_b, k_b);
    loss_kernel<<<4096, 256>>>();
    finalize_kernel<<<1, 1>>>((float*)d_out);
}